// round 11
// baseline (speedup 1.0000x reference)
#include <cuda_runtime.h>
#include <cstddef>

#define BB   2
#define LL   512
#define HH   128
#define NH   8
#define HD   16
#define SCS  516   // padded score row stride

// ---------------- scratch (static device globals; no allocs) ----------------
__device__ float g_q  [BB*LL*HH];            // Q projection        [b,l,128]
__device__ float g_ka [BB*LL*HH];            // K + abs_pos_k       [b,l,128]
__device__ float g_va [BB*LL*HH];            // V + abs_pos_v       [b,l,128]

// ---------------- kernel 1: QKV projections as tiled GEMM -------------------
__global__ void __launch_bounds__(256) k_proj(
    const float* __restrict__ x,  const float* __restrict__ apk,
    const float* __restrict__ apv,
    const float* __restrict__ Wq, const float* __restrict__ bq,
    const float* __restrict__ Wk, const float* __restrict__ bk,
    const float* __restrict__ Wv, const float* __restrict__ bv)
{
    __shared__ float Xs[32][68];   // [kc][token]
    __shared__ float Ws[32][36];   // [kc][out]

    int t  = threadIdx.x;
    int m0 = blockIdx.x * 64;      // token tile base
    int n0 = blockIdx.y * 32;      // output tile base
    int z  = blockIdx.z;           // matrix select

    const float* W;  const float* bias; const float* add; float* dst;
    if (z == 0)      { W = Wq; bias = bq; add = nullptr; dst = g_q;  }
    else if (z == 1) { W = Wk; bias = bk; add = apk;     dst = g_ka; }
    else             { W = Wv; bias = bv; add = apv;     dst = g_va; }

    int tm = t >> 3;               // 0..31 -> 2 tokens each
    int tn = t & 7;                // 0..7  -> 4 outputs each

    float4 acc0 = make_float4(0.f,0.f,0.f,0.f);
    float4 acc1 = make_float4(0.f,0.f,0.f,0.f);

    for (int k0 = 0; k0 < HH; k0 += 32) {
        {
            int idx = t;
#pragma unroll
            for (int rep = 0; rep < 2; rep++, idx += 256) {
                int m = idx >> 3, k4 = idx & 7;
                float4 v = *reinterpret_cast<const float4*>(
                    &x[(size_t)(m0 + m)*HH + k0 + k4*4]);
                Xs[k4*4+0][m] = v.x; Xs[k4*4+1][m] = v.y;
                Xs[k4*4+2][m] = v.z; Xs[k4*4+3][m] = v.w;
            }
        }
        {
            int kc = t >> 3, n4 = t & 7;
            float4 v = *reinterpret_cast<const float4*>(
                &W[(size_t)(k0 + kc)*HH + n0 + n4*4]);
            *reinterpret_cast<float4*>(&Ws[kc][n4*4]) = v;
        }
        __syncthreads();
#pragma unroll
        for (int kc = 0; kc < 32; kc++) {
            float4 w = *reinterpret_cast<const float4*>(&Ws[kc][tn*4]);
            float x0 = Xs[kc][tm*2 + 0];
            float x1 = Xs[kc][tm*2 + 1];
            acc0.x = fmaf(x0, w.x, acc0.x); acc0.y = fmaf(x0, w.y, acc0.y);
            acc0.z = fmaf(x0, w.z, acc0.z); acc0.w = fmaf(x0, w.w, acc0.w);
            acc1.x = fmaf(x1, w.x, acc1.x); acc1.y = fmaf(x1, w.y, acc1.y);
            acc1.z = fmaf(x1, w.z, acc1.z); acc1.w = fmaf(x1, w.w, acc1.w);
        }
        __syncthreads();
    }

    float4 bz = *reinterpret_cast<const float4*>(&bias[n0 + tn*4]);
    acc0.x += bz.x; acc0.y += bz.y; acc0.z += bz.z; acc0.w += bz.w;
    acc1.x += bz.x; acc1.y += bz.y; acc1.z += bz.z; acc1.w += bz.w;

    size_t o0 = (size_t)(m0 + tm*2 + 0)*HH + n0 + tn*4;
    size_t o1 = (size_t)(m0 + tm*2 + 1)*HH + n0 + tn*4;
    if (add) {
        float4 a0 = *reinterpret_cast<const float4*>(&add[o0]);
        float4 a1 = *reinterpret_cast<const float4*>(&add[o1]);
        acc0.x += a0.x; acc0.y += a0.y; acc0.z += a0.z; acc0.w += a0.w;
        acc1.x += a1.x; acc1.y += a1.y; acc1.z += a1.z; acc1.w += a1.w;
    }
    *reinterpret_cast<float4*>(&dst[o0]) = acc0;
    *reinterpret_cast<float4*>(&dst[o1]) = acc1;
}

// ---------------- kernel 2: fully fused attention per (b,q) -----------------
// phase B: scores[h][k] = (q . (ka[k] + tk[k])) / 4 + mask[k]
//          + L2-prefetch of phase D's time_v rows (fills the phase-C bubble)
// phase C: softmax per head (in smem)
// phase D: ctx = sum_k P[h][k] * (va[k] + tv[k])   (tv now L2-resident)
// phase E: out = ctx @ Wo + bo
// (256,8): the R6/R8-verified best occupancy point (regs capped at 32).
__global__ void __launch_bounds__(256, 8) k_fused(
    const float* __restrict__ time_k,
    const float* __restrict__ time_v,
    const float* __restrict__ mask,
    const float* __restrict__ Wo,
    const float* __restrict__ bo,
    float* __restrict__ out)
{
    int bq = blockIdx.x;                 // b*L + q
    int b  = bq >> 9, q = bq & 511;
    __shared__ __align__(16) float qs[HH];      // q, later ctx
    __shared__ float ms[LL];                    // mask, later out-proj partials
    __shared__ __align__(16) float sc[NH*SCS];  // scores -> probs
    __shared__ float4 accbuf[8*32];

    int t = threadIdx.x, w = t >> 5, l = t & 31;

    if (t < HH) qs[t] = g_q[(size_t)bq*HH + t];
    {
        const float* mrow = mask + ((size_t)b*LL + q)*LL;
        for (int k = t; k < LL; k += 256) ms[k] = mrow[k];
    }
    __syncthreads();

    int h  = l >> 2;
    int hb = h * SCS;
    int k0 = w * 64;
    float4 qv = reinterpret_cast<const float4*>(qs)[l];

    const float4* kab = reinterpret_cast<const float4*>(g_ka + (size_t)b*(LL*HH)) + l;
    const float4* vab = reinterpret_cast<const float4*>(g_va + (size_t)b*(LL*HH)) + l;
    const float4* tvb = reinterpret_cast<const float4*>(
        time_v + (size_t)bq * (LL*HH)) + l;

    // ---- phase B ----
    {
        const float4* tkb = reinterpret_cast<const float4*>(
            time_k + (size_t)bq * (LL*HH)) + l;
        for (int k = k0; k < k0 + 64; k += 8) {
            float4 a[8], c[8];
#pragma unroll
            for (int r = 0; r < 8; r++) a[r] = tkb[(size_t)(k+r)*32];
#pragma unroll
            for (int r = 0; r < 8; r++) c[r] = kab[(size_t)(k+r)*32];
            // L2-prefetch the exact time_v rows phase D will consume.
            // Same (bq, k, lane) indexing -> always in-bounds; no dest reg.
#pragma unroll
            for (int r = 0; r < 8; r++)
                asm volatile("prefetch.global.L2 [%0];"
                             :: "l"(tvb + (size_t)(k+r)*32));
            float p[8];
#pragma unroll
            for (int r = 0; r < 8; r++) {
                p[r] = (a[r].x+c[r].x)*qv.x + (a[r].y+c[r].y)*qv.y
                     + (a[r].z+c[r].z)*qv.z + (a[r].w+c[r].w)*qv.w;
            }
#pragma unroll
            for (int r = 0; r < 8; r++) {
                p[r] += __shfl_xor_sync(0xffffffffu, p[r], 1);
                p[r] += __shfl_xor_sync(0xffffffffu, p[r], 2);
            }
            if ((l & 3) == 0) {
#pragma unroll
                for (int r = 0; r < 8; r++)
                    sc[hb+k+r] = p[r] * 0.25f + ms[k+r];
            }
        }
    }
    __syncthreads();

    // ---- phase C: softmax, one warp per head ----
    {
        float* row = sc + w * SCS;
        float mx = -1e30f;
        for (int k = l; k < LL; k += 32) mx = fmaxf(mx, row[k]);
#pragma unroll
        for (int o = 16; o; o >>= 1) mx = fmaxf(mx, __shfl_xor_sync(0xffffffffu, mx, o));
        float s = 0.f;
        for (int k = l; k < LL; k += 32) {
            float e = __expf(row[k] - mx);
            row[k] = e; s += e;
        }
#pragma unroll
        for (int o = 16; o; o >>= 1) s += __shfl_xor_sync(0xffffffffu, s, o);
        float inv = 1.f / s;
        for (int k = l; k < LL; k += 32) row[k] *= inv;
    }
    __syncthreads();

    // ---- phase D ----
    {
        float4 accA = make_float4(0.f, 0.f, 0.f, 0.f);
        float4 accB = make_float4(0.f, 0.f, 0.f, 0.f);
        for (int k = k0; k < k0 + 64; k += 8) {
            float4 a[8], c[8];
#pragma unroll
            for (int r = 0; r < 8; r++) a[r] = tvb[(size_t)(k+r)*32];
#pragma unroll
            for (int r = 0; r < 8; r++) c[r] = vab[(size_t)(k+r)*32];
            float p[8];
#pragma unroll
            for (int r = 0; r < 8; r++) p[r] = sc[hb+k+r];
#pragma unroll
            for (int r = 0; r < 8; r += 2) {
                accA.x = fmaf(p[r], a[r].x+c[r].x, accA.x);
                accA.y = fmaf(p[r], a[r].y+c[r].y, accA.y);
                accA.z = fmaf(p[r], a[r].z+c[r].z, accA.z);
                accA.w = fmaf(p[r], a[r].w+c[r].w, accA.w);
                accB.x = fmaf(p[r+1], a[r+1].x+c[r+1].x, accB.x);
                accB.y = fmaf(p[r+1], a[r+1].y+c[r+1].y, accB.y);
                accB.z = fmaf(p[r+1], a[r+1].z+c[r+1].z, accB.z);
                accB.w = fmaf(p[r+1], a[r+1].w+c[r+1].w, accB.w);
            }
        }
        accA.x += accB.x; accA.y += accB.y; accA.z += accB.z; accA.w += accB.w;
        accbuf[w*32 + l] = accA;
    }
    __syncthreads();
    if (t < 32) {
        float4 s = accbuf[t];
#pragma unroll
        for (int ww = 1; ww < 8; ww++) {
            float4 u = accbuf[ww*32 + t];
            s.x += u.x; s.y += u.y; s.z += u.z; s.w += u.w;
        }
        reinterpret_cast<float4*>(qs)[t] = s;   // ctx row into smem
    }
    __syncthreads();

    // ---- phase E: out[bq] = ctx @ Wo + bo (split-K over 2 thread halves) ----
    {
        int j = t & 127, half = t >> 7;
        const float* Wrow = Wo + (size_t)(half*64)*HH + j;
        float a = 0.f;
#pragma unroll 8
        for (int i = 0; i < 64; i++)
            a = fmaf(qs[half*64 + i], Wrow[(size_t)i*HH], a);
        ms[half*128 + j] = a;                   // reuse mask smem as reducer
    }
    __syncthreads();
    if (t < HH)
        out[(size_t)bq*HH + t] = ms[t] + ms[128 + t] + bo[t];
}

// ---------------- launch ----------------------------------------------------
extern "C" void kernel_launch(void* const* d_in, const int* in_sizes, int n_in,
                              void* d_out, int out_size)
{
    const float* x      = (const float*)d_in[0];
    const float* time_k = (const float*)d_in[1];
    const float* time_v = (const float*)d_in[2];
    const float* apk    = (const float*)d_in[3];
    const float* apv    = (const float*)d_in[4];
    const float* mask   = (const float*)d_in[5];
    const float* Wq     = (const float*)d_in[6];
    const float* bq     = (const float*)d_in[7];
    const float* Wk     = (const float*)d_in[8];
    const float* bk     = (const float*)d_in[9];
    const float* Wv     = (const float*)d_in[10];
    const float* bv     = (const float*)d_in[11];
    const float* Wo     = (const float*)d_in[12];
    const float* bo     = (const float*)d_in[13];

    {
        dim3 g(16, 4, 3);     // 16 token tiles x 4 output tiles x 3 matrices
        k_proj<<<g, 256>>>(x, apk, apv, Wq, bq, Wk, bk, Wv, bv);
    }
    k_fused<<<BB*LL, 256>>>(time_k, time_v, mask, Wo, bo, (float*)d_out);
}

// round 12
// speedup vs baseline: 1.4496x; 1.4496x over previous
#include <cuda_runtime.h>
#include <cstddef>

#define BB   2
#define LL   512
#define HH   128
#define NH   8
#define HD   16

// ---------------- scratch (static device globals; no allocs) ----------------
__device__ float g_q  [BB*LL*HH];            // Q projection        [b,l,128]
__device__ float g_ka [BB*LL*HH];            // K + abs_pos_k       [b,l,128]
__device__ float g_va [BB*LL*HH];            // V + abs_pos_v       [b,l,128]

// ---------------- kernel 1: QKV projections as tiled GEMM -------------------
__global__ void __launch_bounds__(256) k_proj(
    const float* __restrict__ x,  const float* __restrict__ apk,
    const float* __restrict__ apv,
    const float* __restrict__ Wq, const float* __restrict__ bq,
    const float* __restrict__ Wk, const float* __restrict__ bk,
    const float* __restrict__ Wv, const float* __restrict__ bv)
{
    __shared__ float Xs[32][68];   // [kc][token]
    __shared__ float Ws[32][36];   // [kc][out]

    int t  = threadIdx.x;
    int m0 = blockIdx.x * 64;      // token tile base
    int n0 = blockIdx.y * 32;      // output tile base
    int z  = blockIdx.z;           // matrix select

    const float* W;  const float* bias; const float* add; float* dst;
    if (z == 0)      { W = Wq; bias = bq; add = nullptr; dst = g_q;  }
    else if (z == 1) { W = Wk; bias = bk; add = apk;     dst = g_ka; }
    else             { W = Wv; bias = bv; add = apv;     dst = g_va; }

    int tm = t >> 3;               // 0..31 -> 2 tokens each
    int tn = t & 7;                // 0..7  -> 4 outputs each

    float4 acc0 = make_float4(0.f,0.f,0.f,0.f);
    float4 acc1 = make_float4(0.f,0.f,0.f,0.f);

    for (int k0 = 0; k0 < HH; k0 += 32) {
        {
            int idx = t;
#pragma unroll
            for (int rep = 0; rep < 2; rep++, idx += 256) {
                int m = idx >> 3, k4 = idx & 7;
                float4 v = *reinterpret_cast<const float4*>(
                    &x[(size_t)(m0 + m)*HH + k0 + k4*4]);
                Xs[k4*4+0][m] = v.x; Xs[k4*4+1][m] = v.y;
                Xs[k4*4+2][m] = v.z; Xs[k4*4+3][m] = v.w;
            }
        }
        {
            int kc = t >> 3, n4 = t & 7;
            float4 v = *reinterpret_cast<const float4*>(
                &W[(size_t)(k0 + kc)*HH + n0 + n4*4]);
            *reinterpret_cast<float4*>(&Ws[kc][n4*4]) = v;
        }
        __syncthreads();
#pragma unroll
        for (int kc = 0; kc < 32; kc++) {
            float4 w = *reinterpret_cast<const float4*>(&Ws[kc][tn*4]);
            float x0 = Xs[kc][tm*2 + 0];
            float x1 = Xs[kc][tm*2 + 1];
            acc0.x = fmaf(x0, w.x, acc0.x); acc0.y = fmaf(x0, w.y, acc0.y);
            acc0.z = fmaf(x0, w.z, acc0.z); acc0.w = fmaf(x0, w.w, acc0.w);
            acc1.x = fmaf(x1, w.x, acc1.x); acc1.y = fmaf(x1, w.y, acc1.y);
            acc1.z = fmaf(x1, w.z, acc1.z); acc1.w = fmaf(x1, w.w, acc1.w);
        }
        __syncthreads();
    }

    float4 bz = *reinterpret_cast<const float4*>(&bias[n0 + tn*4]);
    acc0.x += bz.x; acc0.y += bz.y; acc0.z += bz.z; acc0.w += bz.w;
    acc1.x += bz.x; acc1.y += bz.y; acc1.z += bz.z; acc1.w += bz.w;

    size_t o0 = (size_t)(m0 + tm*2 + 0)*HH + n0 + tn*4;
    size_t o1 = (size_t)(m0 + tm*2 + 1)*HH + n0 + tn*4;
    if (add) {
        float4 a0 = *reinterpret_cast<const float4*>(&add[o0]);
        float4 a1 = *reinterpret_cast<const float4*>(&add[o1]);
        acc0.x += a0.x; acc0.y += a0.y; acc0.z += a0.z; acc0.w += a0.w;
        acc1.x += a1.x; acc1.y += a1.y; acc1.z += a1.z; acc1.w += a1.w;
    }
    *reinterpret_cast<float4*>(&dst[o0]) = acc0;
    *reinterpret_cast<float4*>(&dst[o1]) = acc1;
}

// ---------------- kernel 2: single-pass online-softmax attention ------------
// One streaming loop per (b,q): load tk/ka/tv/va rows together, compute score,
// online-softmax accumulate e^{s-m}*(tv+va). No phase barriers, each byte of
// time_k/time_v read exactly once, DRAM demand continuous.
// Epilogue: cross-warp softmax merge + out = ctx @ Wo + bo.
__global__ void __launch_bounds__(256, 4) k_fused(
    const float* __restrict__ time_k,
    const float* __restrict__ time_v,
    const float* __restrict__ mask,
    const float* __restrict__ Wo,
    const float* __restrict__ bo,
    float* __restrict__ out)
{
    int bq = blockIdx.x;                 // b*L + q
    int b  = bq >> 9, q = bq & 511;
    __shared__ __align__(16) float qs[HH];      // q, later ctx
    __shared__ float ms[LL];                    // mask, later out-proj partials
    __shared__ float4 accbuf[8*32];             // per-warp partial ctx
    __shared__ float mbuf[8*NH], sbuf[8*NH];    // per-warp per-head (m, s)

    int t = threadIdx.x, w = t >> 5, l = t & 31;

    if (t < HH) qs[t] = g_q[(size_t)bq*HH + t];
    {
        const float* mrow = mask + ((size_t)b*LL + q)*LL;
        for (int k = t; k < LL; k += 256) ms[k] = mrow[k];
    }
    __syncthreads();

    int h  = l >> 2;
    int k0 = w * 64;
    float4 qv = reinterpret_cast<const float4*>(qs)[l];

    const float4* kab = reinterpret_cast<const float4*>(g_ka + (size_t)b*(LL*HH)) + l;
    const float4* vab = reinterpret_cast<const float4*>(g_va + (size_t)b*(LL*HH)) + l;
    const float4* tkb = reinterpret_cast<const float4*>(time_k + (size_t)bq*(LL*HH)) + l;
    const float4* tvb = reinterpret_cast<const float4*>(time_v + (size_t)bq*(LL*HH)) + l;

    float  m_run = -1e30f, s_run = 0.f;
    float4 acc = make_float4(0.f, 0.f, 0.f, 0.f);

    for (int k = k0; k < k0 + 64; k += 2) {
        // 8 outstanding LDG.128 per lane
        float4 a0 = tkb[(size_t)(k+0)*32];
        float4 a1 = tkb[(size_t)(k+1)*32];
        float4 c0 = kab[(size_t)(k+0)*32];
        float4 c1 = kab[(size_t)(k+1)*32];
        float4 b0 = tvb[(size_t)(k+0)*32];
        float4 b1 = tvb[(size_t)(k+1)*32];
        float4 d0 = vab[(size_t)(k+0)*32];
        float4 d1 = vab[(size_t)(k+1)*32];

        float p0 = (a0.x+c0.x)*qv.x + (a0.y+c0.y)*qv.y
                 + (a0.z+c0.z)*qv.z + (a0.w+c0.w)*qv.w;
        float p1 = (a1.x+c1.x)*qv.x + (a1.y+c1.y)*qv.y
                 + (a1.z+c1.z)*qv.z + (a1.w+c1.w)*qv.w;
        // quad reduce -> full head dot on all 4 lanes
        p0 += __shfl_xor_sync(0xffffffffu, p0, 1);
        p0 += __shfl_xor_sync(0xffffffffu, p0, 2);
        p1 += __shfl_xor_sync(0xffffffffu, p1, 1);
        p1 += __shfl_xor_sync(0xffffffffu, p1, 2);

        float s0 = fmaf(p0, 0.25f, ms[k  ]);
        float s1 = fmaf(p1, 0.25f, ms[k+1]);

        float mnew  = fmaxf(m_run, fmaxf(s0, s1));
        float scale = __expf(m_run - mnew);
        float e0    = __expf(s0 - mnew);
        float e1    = __expf(s1 - mnew);
        s_run = fmaf(s_run, scale, e0 + e1);

        acc.x = fmaf(acc.x, scale, fmaf(e0, b0.x+d0.x, e1*(b1.x+d1.x)));
        acc.y = fmaf(acc.y, scale, fmaf(e0, b0.y+d0.y, e1*(b1.y+d1.y)));
        acc.z = fmaf(acc.z, scale, fmaf(e0, b0.z+d0.z, e1*(b1.z+d1.z)));
        acc.w = fmaf(acc.w, scale, fmaf(e0, b0.w+d0.w, e1*(b1.w+d1.w)));
        m_run = mnew;
    }

    accbuf[w*32 + l] = acc;
    if ((l & 3) == 0) {                 // m/s identical across the quad
        mbuf[w*NH + h] = m_run;
        sbuf[w*NH + h] = s_run;
    }
    __syncthreads();

    // ---- cross-warp softmax merge (32 lanes, one per float4 of ctx) ----
    if (t < 32) {
        int hh = t >> 2;
        float M = -1e30f;
#pragma unroll
        for (int ww = 0; ww < 8; ww++) M = fmaxf(M, mbuf[ww*NH + hh]);
        float4 tot = make_float4(0.f, 0.f, 0.f, 0.f);
        float  st  = 0.f;
#pragma unroll
        for (int ww = 0; ww < 8; ww++) {
            float f = __expf(mbuf[ww*NH + hh] - M);
            float4 u = accbuf[ww*32 + t];
            tot.x = fmaf(f, u.x, tot.x);
            tot.y = fmaf(f, u.y, tot.y);
            tot.z = fmaf(f, u.z, tot.z);
            tot.w = fmaf(f, u.w, tot.w);
            st = fmaf(f, sbuf[ww*NH + hh], st);
        }
        float inv = 1.f / st;
        tot.x *= inv; tot.y *= inv; tot.z *= inv; tot.w *= inv;
        reinterpret_cast<float4*>(qs)[t] = tot;   // ctx row into smem
    }
    __syncthreads();

    // ---- epilogue: out[bq] = ctx @ Wo + bo (split-K over 2 thread halves) ---
    {
        int j = t & 127, half = t >> 7;
        const float* Wrow = Wo + (size_t)(half*64)*HH + j;
        float a = 0.f;
#pragma unroll 8
        for (int i = 0; i < 64; i++)
            a = fmaf(qs[half*64 + i], Wrow[(size_t)i*HH], a);
        ms[half*128 + j] = a;                   // reuse mask smem as reducer
    }
    __syncthreads();
    if (t < HH)
        out[(size_t)bq*HH + t] = ms[t] + ms[128 + t] + bo[t];
}

// ---------------- launch ----------------------------------------------------
extern "C" void kernel_launch(void* const* d_in, const int* in_sizes, int n_in,
                              void* d_out, int out_size)
{
    const float* x      = (const float*)d_in[0];
    const float* time_k = (const float*)d_in[1];
    const float* time_v = (const float*)d_in[2];
    const float* apk    = (const float*)d_in[3];
    const float* apv    = (const float*)d_in[4];
    const float* mask   = (const float*)d_in[5];
    const float* Wq     = (const float*)d_in[6];
    const float* bq     = (const float*)d_in[7];
    const float* Wk     = (const float*)d_in[8];
    const float* bk     = (const float*)d_in[9];
    const float* Wv     = (const float*)d_in[10];
    const float* bv     = (const float*)d_in[11];
    const float* Wo     = (const float*)d_in[12];
    const float* bo     = (const float*)d_in[13];

    {
        dim3 g(16, 4, 3);     // 16 token tiles x 4 output tiles x 3 matrices
        k_proj<<<g, 256>>>(x, apk, apv, Wq, bq, Wk, bk, Wv, bv);
    }
    k_fused<<<BB*LL, 256>>>(time_k, time_v, mask, Wo, bo, (float*)d_out);
}